// round 8
// baseline (speedup 1.0000x reference)
#include <cuda_runtime.h>
#include <cstdint>
#include <cstddef>

#define MTOK 20480      // B*T
#define EDIM 1024
#define FF   4096
#define TLEN 320
#define NH   16
#define HSZ  64
#define NQKV 3072

// ---------------------------------------------------------------------------
// Helpers (baseline sm_80-level PTX only: mma.sync tf32 + cp.async)
// ---------------------------------------------------------------------------
__device__ __forceinline__ uint32_t smem_u32(const void* p) {
    uint32_t a;
    asm("{ .reg .u64 t; cvta.to.shared.u64 t, %1; cvt.u32.u64 %0, t; }" : "=r"(a) : "l"(p));
    return a;
}
__device__ __forceinline__ float to_tf32(float v) {
    uint32_t b;
    asm("cvt.rna.tf32.f32 %0, %1;" : "=r"(b) : "f"(v));
    return __uint_as_float(b);
}
__device__ __forceinline__ void mma_tf32(float c[4], const uint32_t a[4], const uint32_t b[2]) {
    asm volatile(
        "mma.sync.aligned.m16n8k8.row.col.f32.tf32.tf32.f32 "
        "{%0,%1,%2,%3}, {%4,%5,%6,%7}, {%8,%9}, {%0,%1,%2,%3};"
        : "+f"(c[0]), "+f"(c[1]), "+f"(c[2]), "+f"(c[3])
        : "r"(a[0]), "r"(a[1]), "r"(a[2]), "r"(a[3]), "r"(b[0]), "r"(b[1]));
}
#define CP_ASYNC16(dst, src) \
    asm volatile("cp.async.ca.shared.global [%0], [%1], 16;" :: "r"(dst), "l"(src))
#define CP_COMMIT()  asm volatile("cp.async.commit_group;" ::: "memory")
#define CP_WAIT(n)   asm volatile("cp.async.wait_group %0;" :: "n"(n) : "memory")

// ---------------------------------------------------------------------------
// Scratch (device globals; tf32 = tf32-rounded fp32)
// ---------------------------------------------------------------------------
__device__ float g_h   [MTOK * EDIM];            // LN out (tf32)
__device__ float g_qkv [(size_t)MTOK * NQKV];    // fp32
__device__ float g_at  [MTOK * EDIM];            // attention out (tf32)
__device__ float g_x1  [MTOK * EDIM];            // fp32
__device__ float g_u   [(size_t)MTOK * FF];      // relu out (tf32)
__device__ float g_Wqkv[NQKV * EDIM];            // [N,K] tf32
__device__ float g_Wo  [EDIM * EDIM];
__device__ float g_W1  [FF * EDIM];
__device__ float g_W2  [EDIM * FF];

// ---------------------------------------------------------------------------
// LayerNorm -> tf32-rounded output
// ---------------------------------------------------------------------------
__global__ void ln_kernel(const float* __restrict__ x, const float* __restrict__ w,
                          const float* __restrict__ b, float* __restrict__ out) {
    int row = blockIdx.x;
    const float* xr = x + (size_t)row * EDIM;
    float v[4];
    float s = 0.f, s2 = 0.f;
#pragma unroll
    for (int i = 0; i < 4; i++) {
        v[i] = xr[threadIdx.x + i * 256];
        s += v[i]; s2 += v[i] * v[i];
    }
#pragma unroll
    for (int o = 16; o > 0; o >>= 1) {
        s  += __shfl_xor_sync(0xffffffffu, s, o);
        s2 += __shfl_xor_sync(0xffffffffu, s2, o);
    }
    __shared__ float ss[8], ss2[8];
    int wid = threadIdx.x >> 5;
    if ((threadIdx.x & 31) == 0) { ss[wid] = s; ss2[wid] = s2; }
    __syncthreads();
    s = 0.f; s2 = 0.f;
#pragma unroll
    for (int i = 0; i < 8; i++) { s += ss[i]; s2 += ss2[i]; }
    float mu  = s * (1.f / EDIM);
    float var = s2 * (1.f / EDIM) - mu * mu;
    float inv = rsqrtf(var + 1e-5f);
#pragma unroll
    for (int i = 0; i < 4; i++) {
        int idx = threadIdx.x + i * 256;
        out[(size_t)row * EDIM + idx] = to_tf32((v[i] - mu) * inv * w[idx] + b[idx]);
    }
}

// ---------------------------------------------------------------------------
// Weight prep: transpose to [N,K] (K contiguous) + tf32 round
// ---------------------------------------------------------------------------
__global__ void qkv_transpose_kernel(const float* __restrict__ Wq, const float* __restrict__ Wk,
                                     const float* __restrict__ Wv, float* __restrict__ o) {
    int idx = blockIdx.x * 256 + threadIdx.x;   // n*1024 + k, n in [0,3072)
    int n = idx >> 10, k = idx & 1023;
    int sel = n >> 10, r = n & 1023;
    int h = r >> 6, d = r & 63;
    const float* src = (sel == 0) ? Wq : (sel == 1) ? Wk : Wv;
    o[idx] = to_tf32(src[(h * 1024 + k) * 64 + d]);
}
__global__ void transpose_kernel(const float* __restrict__ W, float* __restrict__ o,
                                 int Kdim, int Ndim) {
    int idx = blockIdx.x * 256 + threadIdx.x;   // n*Kdim + k
    int k = idx % Kdim, n = idx / Kdim;
    o[idx] = to_tf32(W[(size_t)k * Ndim + n]);
}

// ---------------------------------------------------------------------------
// tf32 mma.sync GEMM, 3-stage cp.async pipeline:
//   C[M,N] = act(A[M,K] @ B^T + bias) (+res)
//   A: [M,K] tf32-valued fp32.  B: [N,K] tf32-valued fp32 (K contiguous).
//   BM=BN=128, BK=32, 256 thr, 8 warps (2 M x 4 N), 64x32 warp tile.
//   One __syncthreads + one wait_group per chunk.
// ---------------------------------------------------------------------------
#define SPAD   36                 // smem row stride (floats); mod 32 = 4 -> conflict-free
#define STG    3                  // pipeline stages
#define TILE_F (128 * SPAD)       // floats per tile
#define SMEM_GEMM (STG * 2 * TILE_F * 4)   // bytes = 110592

__device__ __forceinline__ void prefetch_chunk(const float* __restrict__ A,
                                               const float* __restrict__ B, int K,
                                               int mBase, int nBase, int kb,
                                               uint32_t sa, uint32_t sbm, int tid) {
#pragma unroll
    for (int i = 0; i < 4; i++) {
        int id = tid + i * 256;                  // 1024 float4s per tile
        int row = id >> 3, c4 = id & 7;
        uint32_t so = (uint32_t)(row * SPAD + c4 * 4) * 4;
        CP_ASYNC16(sa  + so, A + (size_t)(mBase + row) * K + kb + c4 * 4);
        CP_ASYNC16(sbm + so, B + (size_t)(nBase + row) * K + kb + c4 * 4);
    }
}

__global__ void __launch_bounds__(256, 2)
gemm_tf32(const float* __restrict__ A, const float* __restrict__ B,
          const float* __restrict__ bias, const float* __restrict__ res,
          float* __restrict__ Cf, float* __restrict__ Ct,
          int N, int K, int doRelu)
{
    extern __shared__ float smp[];
    float* sA[STG];
    float* sB[STG];
    uint32_t saA[STG], saB[STG];
#pragma unroll
    for (int s = 0; s < STG; s++) {
        sA[s] = smp + s * TILE_F;
        sB[s] = smp + (STG + s) * TILE_F;
        saA[s] = smem_u32(sA[s]);
        saB[s] = smem_u32(sB[s]);
    }

    int tid = threadIdx.x;
    int wid = tid >> 5, lane = tid & 31;
    int wm = wid & 1, wn = wid >> 1;            // 2 x 4 warp grid
    int r = lane >> 2, kc = lane & 3;
    int mBase = blockIdx.y * 128, nBase = blockIdx.x * 128;

    float acc[4][4][4];
#pragma unroll
    for (int mt = 0; mt < 4; mt++)
#pragma unroll
        for (int nt = 0; nt < 4; nt++)
#pragma unroll
            for (int j = 0; j < 4; j++) acc[mt][nt][j] = 0.f;

    int NC = K >> 5;   // BK=32
    // prologue: stages 0,1
    prefetch_chunk(A, B, K, mBase, nBase, 0,  saA[0], saB[0], tid);
    CP_COMMIT();
    prefetch_chunk(A, B, K, mBase, nBase, 32, saA[1], saB[1], tid);
    CP_COMMIT();

    for (int c = 0; c < NC; c++) {
        CP_WAIT(1);          // chunk c's group complete (c+1 may be in flight)
        __syncthreads();     // also: every warp done reading buffer (c+2)%STG

        if (c + 2 < NC)
            prefetch_chunk(A, B, K, mBase, nBase, (c + 2) * 32,
                           saA[(c + 2) % STG], saB[(c + 2) % STG], tid);
        CP_COMMIT();         // always commit (possibly empty) to keep counts aligned

        const float* cA = sA[c % STG];
        const float* cB = sB[c % STG];
#pragma unroll
        for (int ks = 0; ks < 4; ks++) {
            int k0 = ks * 8;
            uint32_t afr[4][4];
#pragma unroll
            for (int mt = 0; mt < 4; mt++) {
                int base = (wm * 64 + mt * 16 + r) * SPAD + k0 + kc;
                afr[mt][0] = __float_as_uint(cA[base]);
                afr[mt][1] = __float_as_uint(cA[base + 8 * SPAD]);
                afr[mt][2] = __float_as_uint(cA[base + 4]);
                afr[mt][3] = __float_as_uint(cA[base + 8 * SPAD + 4]);
            }
            uint32_t bfr[4][2];
#pragma unroll
            for (int nt = 0; nt < 4; nt++) {
                int base = (wn * 32 + nt * 8 + r) * SPAD + k0 + kc;
                bfr[nt][0] = __float_as_uint(cB[base]);
                bfr[nt][1] = __float_as_uint(cB[base + 4]);
            }
#pragma unroll
            for (int mt = 0; mt < 4; mt++)
#pragma unroll
                for (int nt = 0; nt < 4; nt++)
                    mma_tf32(acc[mt][nt], afr[mt], bfr[nt]);
        }
    }

    // Epilogue: c0/c1 at (row, 2t/2t+1), c2/c3 at (row+8, .)
#pragma unroll
    for (int nt = 0; nt < 4; nt++) {
        int gc = nBase + wn * 32 + nt * 8 + kc * 2;
        float b0 = bias ? bias[gc]     : 0.f;
        float b1 = bias ? bias[gc + 1] : 0.f;
#pragma unroll
        for (int mt = 0; mt < 4; mt++) {
            int gr = mBase + wm * 64 + mt * 16 + r;
#pragma unroll
            for (int half = 0; half < 2; half++) {
                int row = gr + half * 8;
                float v0 = acc[mt][nt][half * 2 + 0] + b0;
                float v1 = acc[mt][nt][half * 2 + 1] + b1;
                if (doRelu) { v0 = fmaxf(v0, 0.f); v1 = fmaxf(v1, 0.f); }
                if (res) {
                    float2 rr = *reinterpret_cast<const float2*>(res + (size_t)row * N + gc);
                    v0 += rr.x; v1 += rr.y;
                }
                if (Cf) {
                    float2 o = { v0, v1 };
                    *reinterpret_cast<float2*>(Cf + (size_t)row * N + gc) = o;
                }
                if (Ct) {
                    float2 o = { to_tf32(v0), to_tf32(v1) };
                    *reinterpret_cast<float2*>(Ct + (size_t)row * N + gc) = o;
                }
            }
        }
    }
}

// ---------------------------------------------------------------------------
// Causal attention: block per (b,h), 320 threads = 1 query row each.
// ---------------------------------------------------------------------------
__global__ void __launch_bounds__(TLEN, 1)
attn_kernel(const float* __restrict__ qkv, float* __restrict__ outT) {
    extern __shared__ float sm[];
    float* Ks = sm;
    float* Vs = sm + TLEN * HSZ;

    int b = blockIdx.x / NH;
    int h = blockIdx.x % NH;
    size_t rowB = (size_t)b * TLEN;
    int hc = h * HSZ;

    int tid = threadIdx.x;
    for (int idx = tid; idx < TLEN * HSZ; idx += TLEN) {
        int rr = idx >> 6, d = idx & 63;
        size_t g = (rowB + rr) * NQKV + hc + d;
        Ks[idx] = qkv[g + 1024];
        Vs[idx] = qkv[g + 2048];
    }
    __syncthreads();

    int t = tid;
    float qr[HSZ];
#pragma unroll
    for (int d = 0; d < HSZ; d++) qr[d] = qkv[(rowB + t) * NQKV + hc + d];

    float m = -1e30f, l = 0.f;
    float acc[HSZ];
#pragma unroll
    for (int d = 0; d < HSZ; d++) acc[d] = 0.f;

    const float scale = 0.03125f;  // E^-0.5 (reference scales by full E)
    for (int s = 0; s <= t; s++) {
        const float* kr = Ks + s * HSZ;
        float d0 = 0.f, d1 = 0.f, d2 = 0.f, d3 = 0.f;
#pragma unroll
        for (int d = 0; d < HSZ; d += 4) {
            d0 = fmaf(qr[d],     kr[d],     d0);
            d1 = fmaf(qr[d + 1], kr[d + 1], d1);
            d2 = fmaf(qr[d + 2], kr[d + 2], d2);
            d3 = fmaf(qr[d + 3], kr[d + 3], d3);
        }
        float sc = ((d0 + d1) + (d2 + d3)) * scale;
        float mn = fmaxf(m, sc);
        float corr = __expf(m - mn);
        float p = __expf(sc - mn);
        l = l * corr + p;
        m = mn;
        const float* vr = Vs + s * HSZ;
#pragma unroll
        for (int d = 0; d < HSZ; d++) acc[d] = fmaf(p, vr[d], acc[d] * corr);
    }

    float invl = 1.f / l;
    size_t ob = (rowB + t) * EDIM + hc;
#pragma unroll
    for (int d = 0; d < HSZ; d++) outT[ob + d] = to_tf32(acc[d] * invl);
}

// ---------------------------------------------------------------------------
// Launch
// ---------------------------------------------------------------------------
extern "C" void kernel_launch(void* const* d_in, const int* in_sizes, int n_in,
                              void* d_out, int out_size) {
    const float* x    = (const float*)d_in[0];
    const float* Wq   = (const float*)d_in[1];
    const float* Wk   = (const float*)d_in[2];
    const float* Wv   = (const float*)d_in[3];
    const float* Wo   = (const float*)d_in[4];
    const float* bo   = (const float*)d_in[5];
    const float* W1   = (const float*)d_in[6];
    const float* b1   = (const float*)d_in[7];
    const float* W2   = (const float*)d_in[8];
    const float* b2   = (const float*)d_in[9];
    const float* ln1w = (const float*)d_in[10];
    const float* ln1b = (const float*)d_in[11];
    const float* ln2w = (const float*)d_in[12];
    const float* ln2b = (const float*)d_in[13];
    float* out = (float*)d_out;

    void* p;
#define SYM(var, sym) cudaGetSymbolAddress(&p, sym); float* var = (float*)p;
    SYM(h,    g_h)
    SYM(qkv,  g_qkv)
    SYM(at,   g_at)
    SYM(x1,   g_x1)
    SYM(u,    g_u)
    SYM(Wqkv, g_Wqkv)
    SYM(WoT,  g_Wo)
    SYM(W1T,  g_W1)
    SYM(W2T,  g_W2)
#undef SYM

    const int smemAttn = 2 * TLEN * HSZ * (int)sizeof(float);  // 160 KB
    cudaFuncSetAttribute(attn_kernel, cudaFuncAttributeMaxDynamicSharedMemorySize, smemAttn);
    cudaFuncSetAttribute(gemm_tf32, cudaFuncAttributeMaxDynamicSharedMemorySize, SMEM_GEMM);

    // Weight prep (tf32-rounded, [N,K] layout)
    qkv_transpose_kernel<<<NQKV * EDIM / 256, 256>>>(Wq, Wk, Wv, Wqkv);
    transpose_kernel<<<EDIM * EDIM / 256, 256>>>(Wo, WoT, EDIM, EDIM);
    transpose_kernel<<<FF * EDIM / 256, 256>>>(W1, W1T, EDIM, FF);
    transpose_kernel<<<EDIM * FF / 256, 256>>>(W2, W2T, FF, EDIM);

    dim3 blk(256);
    // 1) LN1 -> h (tf32)
    ln_kernel<<<MTOK, 256>>>(x, ln1w, ln1b, h);
    // 2) fused QKV: [M,1024] x [3072,1024]^T -> qkv fp32
    gemm_tf32<<<dim3(NQKV / 128, MTOK / 128), blk, SMEM_GEMM>>>(
        h, Wqkv, nullptr, nullptr, qkv, nullptr, NQKV, EDIM, 0);
    // 3) attention -> at (tf32)
    attn_kernel<<<64 * NH, TLEN, smemAttn>>>(qkv, at);
    // 4) O-proj + bo + residual(x) -> x1 fp32
    gemm_tf32<<<dim3(EDIM / 128, MTOK / 128), blk, SMEM_GEMM>>>(
        at, WoT, bo, x, x1, nullptr, EDIM, EDIM, 0);
    // 5) LN2 -> h (tf32)
    ln_kernel<<<MTOK, 256>>>(x1, ln2w, ln2b, h);
    // 6) FFN up + b1 + ReLU -> u (tf32)
    gemm_tf32<<<dim3(FF / 128, MTOK / 128), blk, SMEM_GEMM>>>(
        h, W1T, b1, nullptr, nullptr, u, FF, EDIM, 1);
    // 7) FFN down + b2 + residual(x1) -> out fp32
    gemm_tf32<<<dim3(EDIM / 128, MTOK / 128), blk, SMEM_GEMM>>>(
        u, W2T, b2, x1, out, nullptr, EDIM, FF, 0);
}

// round 10
// speedup vs baseline: 1.5427x; 1.5427x over previous
#include <cuda_runtime.h>
#include <cuda_fp16.h>
#include <cstdint>
#include <cstddef>

#define MTOK 20480      // B*T
#define EDIM 1024
#define FF   4096
#define TLEN 320
#define NH   16
#define HSZ  64
#define NQKV 3072

// ---------------------------------------------------------------------------
// Helpers (baseline sm_80-level PTX only: fp16 mma.sync + cp.async)
// ---------------------------------------------------------------------------
__device__ __forceinline__ void mma_f16(float c[4], const uint32_t a[4], const uint32_t b[2]) {
    asm volatile(
        "mma.sync.aligned.m16n8k16.row.col.f32.f16.f16.f32 "
        "{%0,%1,%2,%3}, {%4,%5,%6,%7}, {%8,%9}, {%0,%1,%2,%3};"
        : "+f"(c[0]), "+f"(c[1]), "+f"(c[2]), "+f"(c[3])
        : "r"(a[0]), "r"(a[1]), "r"(a[2]), "r"(a[3]), "r"(b[0]), "r"(b[1]));
}
#define CP_ASYNC16(dst, src) \
    asm volatile("cp.async.ca.shared.global [%0], [%1], 16;" :: "r"(dst), "l"(src))
#define CP_COMMIT()  asm volatile("cp.async.commit_group;" ::: "memory")
#define CP_WAIT(n)   asm volatile("cp.async.wait_group %0;" :: "n"(n) : "memory")
__device__ __forceinline__ uint32_t smem_u32(const void* p) {
    uint32_t a;
    asm("{ .reg .u64 t; cvta.to.shared.u64 t, %1; cvt.u32.u64 %0, t; }" : "=r"(a) : "l"(p));
    return a;
}

// ---------------------------------------------------------------------------
// Scratch (device globals)
// ---------------------------------------------------------------------------
__device__ __half g_h   [MTOK * EDIM];            // LN out
__device__ float  g_qkv [(size_t)MTOK * NQKV];    // fp32 (attention reads this)
__device__ __half g_at  [MTOK * EDIM];            // attention out
__device__ float  g_x1  [MTOK * EDIM];            // fp32 residual stream
__device__ __half g_u   [(size_t)MTOK * FF];      // relu out
__device__ __half g_Wqkv[NQKV * EDIM];            // [N,K]
__device__ __half g_Wo  [EDIM * EDIM];
__device__ __half g_W1  [FF * EDIM];
__device__ __half g_W2  [EDIM * FF];

// ---------------------------------------------------------------------------
// LayerNorm -> fp16 output
// ---------------------------------------------------------------------------
__global__ void ln_kernel(const float* __restrict__ x, const float* __restrict__ w,
                          const float* __restrict__ b, __half* __restrict__ out) {
    int row = blockIdx.x;
    const float* xr = x + (size_t)row * EDIM;
    float v[4];
    float s = 0.f, s2 = 0.f;
#pragma unroll
    for (int i = 0; i < 4; i++) {
        v[i] = xr[threadIdx.x + i * 256];
        s += v[i]; s2 += v[i] * v[i];
    }
#pragma unroll
    for (int o = 16; o > 0; o >>= 1) {
        s  += __shfl_xor_sync(0xffffffffu, s, o);
        s2 += __shfl_xor_sync(0xffffffffu, s2, o);
    }
    __shared__ float ss[8], ss2[8];
    int wid = threadIdx.x >> 5;
    if ((threadIdx.x & 31) == 0) { ss[wid] = s; ss2[wid] = s2; }
    __syncthreads();
    s = 0.f; s2 = 0.f;
#pragma unroll
    for (int i = 0; i < 8; i++) { s += ss[i]; s2 += ss2[i]; }
    float mu  = s * (1.f / EDIM);
    float var = s2 * (1.f / EDIM) - mu * mu;
    float inv = rsqrtf(var + 1e-5f);
#pragma unroll
    for (int i = 0; i < 4; i++) {
        int idx = threadIdx.x + i * 256;
        out[(size_t)row * EDIM + idx] = __float2half_rn((v[i] - mu) * inv * w[idx] + b[idx]);
    }
}

// ---------------------------------------------------------------------------
// Weight prep: transpose to [N,K] (K contiguous) + fp16 convert
// ---------------------------------------------------------------------------
__global__ void qkv_transpose_kernel(const float* __restrict__ Wq, const float* __restrict__ Wk,
                                     const float* __restrict__ Wv, __half* __restrict__ o) {
    int idx = blockIdx.x * 256 + threadIdx.x;   // n*1024 + k, n in [0,3072)
    int n = idx >> 10, k = idx & 1023;
    int sel = n >> 10, r = n & 1023;
    int h = r >> 6, d = r & 63;
    const float* src = (sel == 0) ? Wq : (sel == 1) ? Wk : Wv;
    o[idx] = __float2half_rn(src[(h * 1024 + k) * 64 + d]);
}
__global__ void transpose_kernel(const float* __restrict__ W, __half* __restrict__ o,
                                 int Kdim, int Ndim) {
    int idx = blockIdx.x * 256 + threadIdx.x;   // n*Kdim + k
    int k = idx % Kdim, n = idx / Kdim;
    o[idx] = __float2half_rn(W[(size_t)k * Ndim + n]);
}

// ---------------------------------------------------------------------------
// fp16 mma.sync GEMM, 3-stage cp.async pipeline:
//   C[M,N] = act(A[M,K] @ B^T + bias) (+res)
//   A: [M,K] fp16.  B: [N,K] fp16 (K contiguous).
//   BM=BN=128, BK=64, 256 thr, 8 warps (2 M x 4 N), 64x32 warp tile.
// ---------------------------------------------------------------------------
#define SPADH  72                  // halves per smem row (144 B; 4 banks mod 32)
#define STG    3
#define TILE_H (128 * SPADH)       // halves per tile
#define SMEM_GEMM (STG * 2 * TILE_H * 2)   // bytes = 110592

__device__ __forceinline__ void prefetch_chunk(const __half* __restrict__ A,
                                               const __half* __restrict__ B, int K,
                                               int mBase, int nBase, int kb,
                                               uint32_t sa, uint32_t sbm, int tid) {
#pragma unroll
    for (int i = 0; i < 4; i++) {
        int id = tid + i * 256;                  // 1024 16B-chunks per tile
        int row = id >> 3, c8 = id & 7;          // 8 x 8halves = 64 halves/row
        uint32_t so = (uint32_t)(row * SPADH + c8 * 8) * 2;
        CP_ASYNC16(sa  + so, A + (size_t)(mBase + row) * K + kb + c8 * 8);
        CP_ASYNC16(sbm + so, B + (size_t)(nBase + row) * K + kb + c8 * 8);
    }
}

__global__ void __launch_bounds__(256, 2)
gemm_f16(const __half* __restrict__ A, const __half* __restrict__ B,
         const float* __restrict__ bias, const float* __restrict__ res,
         float* __restrict__ Cf, __half* __restrict__ Ch,
         int N, int K, int doRelu)
{
    extern __shared__ __half smp[];
    const __half* sA[STG];
    const __half* sB[STG];
    uint32_t saA[STG], saB[STG];
#pragma unroll
    for (int s = 0; s < STG; s++) {
        sA[s] = smp + s * TILE_H;
        sB[s] = smp + (STG + s) * TILE_H;
        saA[s] = smem_u32(sA[s]);
        saB[s] = smem_u32(sB[s]);
    }

    int tid = threadIdx.x;
    int wid = tid >> 5, lane = tid & 31;
    int wm = wid & 1, wn = wid >> 1;            // 2 x 4 warp grid
    int r = lane >> 2, kc = lane & 3;           // groupID, threadID-in-group
    int mBase = blockIdx.y * 128, nBase = blockIdx.x * 128;

    float acc[4][4][4];
#pragma unroll
    for (int mt = 0; mt < 4; mt++)
#pragma unroll
        for (int nt = 0; nt < 4; nt++)
#pragma unroll
            for (int j = 0; j < 4; j++) acc[mt][nt][j] = 0.f;

    int NC = K >> 6;   // BK=64
    prefetch_chunk(A, B, K, mBase, nBase, 0,  saA[0], saB[0], tid);
    CP_COMMIT();
    prefetch_chunk(A, B, K, mBase, nBase, 64, saA[1], saB[1], tid);
    CP_COMMIT();

    for (int c = 0; c < NC; c++) {
        CP_WAIT(1);
        __syncthreads();

        if (c + 2 < NC)
            prefetch_chunk(A, B, K, mBase, nBase, (c + 2) * 64,
                           saA[(c + 2) % STG], saB[(c + 2) % STG], tid);
        CP_COMMIT();

        const __half* cA = sA[c % STG];
        const __half* cB = sB[c % STG];
#pragma unroll
        for (int ks = 0; ks < 4; ks++) {
            int k0 = ks * 16;
            // A fragments: a0=(row,k) a1=(row+8,k) a2=(row,k+8) a3=(row+8,k+8), half2 each
            uint32_t afr[4][4];
#pragma unroll
            for (int mt = 0; mt < 4; mt++) {
                int base = (wm * 64 + mt * 16 + r) * SPADH + k0 + 2 * kc;
                afr[mt][0] = *reinterpret_cast<const uint32_t*>(cA + base);
                afr[mt][1] = *reinterpret_cast<const uint32_t*>(cA + base + 8 * SPADH);
                afr[mt][2] = *reinterpret_cast<const uint32_t*>(cA + base + 8);
                afr[mt][3] = *reinterpret_cast<const uint32_t*>(cA + base + 8 * SPADH + 8);
            }
            // B fragments: b0=(n,k..k+1) b1=(n,k+8..k+9)
            uint32_t bfr[4][2];
#pragma unroll
            for (int nt = 0; nt < 4; nt++) {
                int base = (wn * 32 + nt * 8 + r) * SPADH + k0 + 2 * kc;
                bfr[nt][0] = *reinterpret_cast<const uint32_t*>(cB + base);
                bfr[nt][1] = *reinterpret_cast<const uint32_t*>(cB + base + 8);
            }
#pragma unroll
            for (int mt = 0; mt < 4; mt++)
#pragma unroll
                for (int nt = 0; nt < 4; nt++)
                    mma_f16(acc[mt][nt], afr[mt], bfr[nt]);
        }
    }

    // Epilogue: c0/c1 at (row, 2kc/2kc+1), c2/c3 at (row+8, .)
#pragma unroll
    for (int nt = 0; nt < 4; nt++) {
        int gc = nBase + wn * 32 + nt * 8 + kc * 2;
        float b0 = bias ? bias[gc]     : 0.f;
        float b1 = bias ? bias[gc + 1] : 0.f;
#pragma unroll
        for (int mt = 0; mt < 4; mt++) {
            int gr = mBase + wm * 64 + mt * 16 + r;
#pragma unroll
            for (int half = 0; half < 2; half++) {
                int row = gr + half * 8;
                float v0 = acc[mt][nt][half * 2 + 0] + b0;
                float v1 = acc[mt][nt][half * 2 + 1] + b1;
                if (doRelu) { v0 = fmaxf(v0, 0.f); v1 = fmaxf(v1, 0.f); }
                if (res) {
                    float2 rr = *reinterpret_cast<const float2*>(res + (size_t)row * N + gc);
                    v0 += rr.x; v1 += rr.y;
                }
                if (Cf) {
                    float2 o = { v0, v1 };
                    *reinterpret_cast<float2*>(Cf + (size_t)row * N + gc) = o;
                }
                if (Ch) {
                    __half2 o = { __float2half_rn(v0), __float2half_rn(v1) };
                    *reinterpret_cast<__half2*>(Ch + (size_t)row * N + gc) = o;
                }
            }
        }
    }
}

// ---------------------------------------------------------------------------
// Causal attention: block per (b,h), 320 threads = 1 query row each.
// Reads fused qkv fp32 [M,3072]; writes fp16 output [M,1024].
// ---------------------------------------------------------------------------
__global__ void __launch_bounds__(TLEN, 1)
attn_kernel(const float* __restrict__ qkv, __half* __restrict__ outH) {
    extern __shared__ float sm[];
    float* Ks = sm;
    float* Vs = sm + TLEN * HSZ;

    int b = blockIdx.x / NH;
    int h = blockIdx.x % NH;
    size_t rowB = (size_t)b * TLEN;
    int hc = h * HSZ;

    int tid = threadIdx.x;
    for (int idx = tid; idx < TLEN * HSZ; idx += TLEN) {
        int rr = idx >> 6, d = idx & 63;
        size_t g = (rowB + rr) * NQKV + hc + d;
        Ks[idx] = qkv[g + 1024];
        Vs[idx] = qkv[g + 2048];
    }
    __syncthreads();

    int t = tid;
    float qr[HSZ];
#pragma unroll
    for (int d = 0; d < HSZ; d++) qr[d] = qkv[(rowB + t) * NQKV + hc + d];

    float m = -1e30f, l = 0.f;
    float acc[HSZ];
#pragma unroll
    for (int d = 0; d < HSZ; d++) acc[d] = 0.f;

    const float scale = 0.03125f;  // E^-0.5 (reference scales by full E)
    for (int s = 0; s <= t; s++) {
        const float* kr = Ks + s * HSZ;
        float d0 = 0.f, d1 = 0.f, d2 = 0.f, d3 = 0.f;
#pragma unroll
        for (int d = 0; d < HSZ; d += 4) {
            d0 = fmaf(qr[d],     kr[d],     d0);
            d1 = fmaf(qr[d + 1], kr[d + 1], d1);
            d2 = fmaf(qr[d + 2], kr[d + 2], d2);
            d3 = fmaf(qr[d + 3], kr[d + 3], d3);
        }
        float sc = ((d0 + d1) + (d2 + d3)) * scale;
        float mn = fmaxf(m, sc);
        float corr = __expf(m - mn);
        float p = __expf(sc - mn);
        l = l * corr + p;
        m = mn;
        const float* vr = Vs + s * HSZ;
#pragma unroll
        for (int d = 0; d < HSZ; d++) acc[d] = fmaf(p, vr[d], acc[d] * corr);
    }

    float invl = 1.f / l;
    size_t ob = (rowB + t) * EDIM + hc;
#pragma unroll
    for (int d = 0; d < HSZ; d++) outH[ob + d] = __float2half_rn(acc[d] * invl);
}

// ---------------------------------------------------------------------------
// Launch
// ---------------------------------------------------------------------------
extern "C" void kernel_launch(void* const* d_in, const int* in_sizes, int n_in,
                              void* d_out, int out_size) {
    const float* x    = (const float*)d_in[0];
    const float* Wq   = (const float*)d_in[1];
    const float* Wk   = (const float*)d_in[2];
    const float* Wv   = (const float*)d_in[3];
    const float* Wo   = (const float*)d_in[4];
    const float* bo   = (const float*)d_in[5];
    const float* W1   = (const float*)d_in[6];
    const float* b1   = (const float*)d_in[7];
    const float* W2   = (const float*)d_in[8];
    const float* b2   = (const float*)d_in[9];
    const float* ln1w = (const float*)d_in[10];
    const float* ln1b = (const float*)d_in[11];
    const float* ln2w = (const float*)d_in[12];
    const float* ln2b = (const float*)d_in[13];
    float* out = (float*)d_out;

    void* p;
#define SYMF(var, sym) cudaGetSymbolAddress(&p, sym); float* var = (float*)p;
#define SYMH(var, sym) cudaGetSymbolAddress(&p, sym); __half* var = (__half*)p;
    SYMH(h,    g_h)
    SYMF(qkv,  g_qkv)
    SYMH(at,   g_at)
    SYMF(x1,   g_x1)
    SYMH(u,    g_u)
    SYMH(Wqkv, g_Wqkv)
    SYMH(WoT,  g_Wo)
    SYMH(W1T,  g_W1)
    SYMH(W2T,  g_W2)
#undef SYMF
#undef SYMH

    const int smemAttn = 2 * TLEN * HSZ * (int)sizeof(float);  // 160 KB
    cudaFuncSetAttribute(attn_kernel, cudaFuncAttributeMaxDynamicSharedMemorySize, smemAttn);
    cudaFuncSetAttribute(gemm_f16, cudaFuncAttributeMaxDynamicSharedMemorySize, SMEM_GEMM);

    // Weight prep (fp16, [N,K] layout)
    qkv_transpose_kernel<<<NQKV * EDIM / 256, 256>>>(Wq, Wk, Wv, Wqkv);
    transpose_kernel<<<EDIM * EDIM / 256, 256>>>(Wo, WoT, EDIM, EDIM);
    transpose_kernel<<<FF * EDIM / 256, 256>>>(W1, W1T, EDIM, FF);
    transpose_kernel<<<EDIM * FF / 256, 256>>>(W2, W2T, FF, EDIM);

    dim3 blk(256);
    // 1) LN1 -> h (fp16)
    ln_kernel<<<MTOK, 256>>>(x, ln1w, ln1b, h);
    // 2) fused QKV: [M,1024] x [3072,1024]^T -> qkv fp32
    gemm_f16<<<dim3(NQKV / 128, MTOK / 128), blk, SMEM_GEMM>>>(
        h, Wqkv, nullptr, nullptr, qkv, nullptr, NQKV, EDIM, 0);
    // 3) attention -> at (fp16)
    attn_kernel<<<64 * NH, TLEN, smemAttn>>>(qkv, at);
    // 4) O-proj + bo + residual(x) -> x1 fp32
    gemm_f16<<<dim3(EDIM / 128, MTOK / 128), blk, SMEM_GEMM>>>(
        at, WoT, bo, x, x1, nullptr, EDIM, EDIM, 0);
    // 5) LN2 -> h (fp16)
    ln_kernel<<<MTOK, 256>>>(x1, ln2w, ln2b, h);
    // 6) FFN up + b1 + ReLU -> u (fp16)
    gemm_f16<<<dim3(FF / 128, MTOK / 128), blk, SMEM_GEMM>>>(
        h, W1T, b1, nullptr, nullptr, u, FF, EDIM, 1);
    // 7) FFN down + b2 + residual(x1) -> out fp32
    gemm_f16<<<dim3(EDIM / 128, MTOK / 128), blk, SMEM_GEMM>>>(
        u, W2T, b2, x1, out, nullptr, EDIM, FF, 0);
}

// round 16
// speedup vs baseline: 1.6427x; 1.0648x over previous
#include <cuda_runtime.h>
#include <cuda_fp16.h>
#include <cstdint>
#include <cstddef>

#define MTOK 20480      // B*T
#define EDIM 1024
#define FF   4096
#define TLEN 320
#define NH   16
#define HSZ  64
#define NQKV 3072

// ---------------------------------------------------------------------------
// Helpers (sm_80 baseline: fp16 mma.sync + cp.async; sm_100 baseline: f32x2)
// ---------------------------------------------------------------------------
__device__ __forceinline__ void mma_f16(float c[4], const uint32_t a[4], const uint32_t b[2]) {
    asm volatile(
        "mma.sync.aligned.m16n8k16.row.col.f32.f16.f16.f32 "
        "{%0,%1,%2,%3}, {%4,%5,%6,%7}, {%8,%9}, {%0,%1,%2,%3};"
        : "+f"(c[0]), "+f"(c[1]), "+f"(c[2]), "+f"(c[3])
        : "r"(a[0]), "r"(a[1]), "r"(a[2]), "r"(a[3]), "r"(b[0]), "r"(b[1]));
}
#define CP_ASYNC16(dst, src) \
    asm volatile("cp.async.ca.shared.global [%0], [%1], 16;" :: "r"(dst), "l"(src))
#define CP_COMMIT()  asm volatile("cp.async.commit_group;" ::: "memory")
#define CP_WAIT(n)   asm volatile("cp.async.wait_group %0;" :: "n"(n) : "memory")
__device__ __forceinline__ uint32_t smem_u32(const void* p) {
    uint32_t a;
    asm("{ .reg .u64 t; cvta.to.shared.u64 t, %1; cvt.u32.u64 %0, t; }" : "=r"(a) : "l"(p));
    return a;
}
// Packed fp32x2 ops (PTX ISA 8.6, sm_100+ baseline). Exact fp32 arithmetic.
#define FMA2(d, a, b)  asm("fma.rn.f32x2 %0, %1, %2, %0;" : "+l"(d) : "l"(a), "l"(b))
#define MUL2(d, c)     asm("mul.rn.f32x2 %0, %0, %1;"     : "+l"(d) : "l"(c))
#define PACK2(d, x)    asm("mov.b64 %0, {%1, %1};" : "=l"(d) : "f"(x))
#define PACK2XY(d, x, y) asm("mov.b64 %0, {%1, %2};" : "=l"(d) : "f"(x), "f"(y))
#define UNPACK2(lo, hi, d) asm("mov.b64 {%0, %1}, %2;" : "=f"(lo), "=f"(hi) : "l"(d))

// ---------------------------------------------------------------------------
// Scratch (device globals)
// ---------------------------------------------------------------------------
__device__ __half g_h   [MTOK * EDIM];            // LN out
__device__ float  g_qkv [(size_t)MTOK * NQKV];    // fp32 (attention reads this)
__device__ __half g_at  [MTOK * EDIM];            // attention out
__device__ float  g_x1  [MTOK * EDIM];            // fp32 residual stream
__device__ __half g_u   [(size_t)MTOK * FF];      // relu out
__device__ __half g_Wqkv[NQKV * EDIM];            // [N,K]
__device__ __half g_Wo  [EDIM * EDIM];
__device__ __half g_W1  [FF * EDIM];
__device__ __half g_W2  [EDIM * FF];

// ---------------------------------------------------------------------------
// LayerNorm -> fp16 output
// ---------------------------------------------------------------------------
__global__ void ln_kernel(const float* __restrict__ x, const float* __restrict__ w,
                          const float* __restrict__ b, __half* __restrict__ out) {
    int row = blockIdx.x;
    const float* xr = x + (size_t)row * EDIM;
    float v[4];
    float s = 0.f, s2 = 0.f;
#pragma unroll
    for (int i = 0; i < 4; i++) {
        v[i] = xr[threadIdx.x + i * 256];
        s += v[i]; s2 += v[i] * v[i];
    }
#pragma unroll
    for (int o = 16; o > 0; o >>= 1) {
        s  += __shfl_xor_sync(0xffffffffu, s, o);
        s2 += __shfl_xor_sync(0xffffffffu, s2, o);
    }
    __shared__ float ss[8], ss2[8];
    int wid = threadIdx.x >> 5;
    if ((threadIdx.x & 31) == 0) { ss[wid] = s; ss2[wid] = s2; }
    __syncthreads();
    s = 0.f; s2 = 0.f;
#pragma unroll
    for (int i = 0; i < 8; i++) { s += ss[i]; s2 += ss2[i]; }
    float mu  = s * (1.f / EDIM);
    float var = s2 * (1.f / EDIM) - mu * mu;
    float inv = rsqrtf(var + 1e-5f);
#pragma unroll
    for (int i = 0; i < 4; i++) {
        int idx = threadIdx.x + i * 256;
        out[(size_t)row * EDIM + idx] = __float2half_rn((v[i] - mu) * inv * w[idx] + b[idx]);
    }
}

// ---------------------------------------------------------------------------
// Weight prep: smem-tiled transposes (coalesced both sides) + fp16 convert
// ---------------------------------------------------------------------------
__global__ void transpose_tiled(const float* __restrict__ W, __half* __restrict__ o,
                                int Kdim, int Ndim) {
    // W: [Kdim, Ndim] row-major -> o: [Ndim, Kdim] (k contiguous)
    __shared__ float tile[32][33];
    int kb = blockIdx.x * 32, nb = blockIdx.y * 32;
    int tx = threadIdx.x & 31, ty = threadIdx.x >> 5;   // 256 thr = 32x8
#pragma unroll
    for (int i = 0; i < 4; i++) {
        int k = kb + ty + i * 8;
        tile[ty + i * 8][tx] = W[(size_t)k * Ndim + nb + tx];
    }
    __syncthreads();
#pragma unroll
    for (int i = 0; i < 4; i++) {
        int n = nb + ty + i * 8;
        o[(size_t)n * Kdim + kb + tx] = __float2half_rn(tile[tx][ty + i * 8]);
    }
}

__global__ void qkv_transpose_tiled(const float* __restrict__ Wq, const float* __restrict__ Wk,
                                    const float* __restrict__ Wv, __half* __restrict__ o) {
    // src sel: (H, K=1024, HS=64) -> o[(sel*1024 + h*64 + d) * 1024 + k]
    __shared__ float tile[32][33];
    int kb = blockIdx.x * 32;
    int db = (blockIdx.y & 1) * 32;
    int hh = blockIdx.y >> 1;            // 0..47 = sel*16 + h
    int sel = hh >> 4, h = hh & 15;
    const float* src = (sel == 0) ? Wq : (sel == 1) ? Wk : Wv;
    int tx = threadIdx.x & 31, ty = threadIdx.x >> 5;
#pragma unroll
    for (int i = 0; i < 4; i++) {
        int k = kb + ty + i * 8;
        tile[ty + i * 8][tx] = src[(size_t)(h * 1024 + k) * 64 + db + tx];
    }
    __syncthreads();
#pragma unroll
    for (int i = 0; i < 4; i++) {
        int d = db + ty + i * 8;
        o[(size_t)(sel * 1024 + h * 64 + d) * 1024 + kb + tx] = __float2half_rn(tile[tx][ty + i * 8]);
    }
}

// ---------------------------------------------------------------------------
// fp16 mma.sync GEMM, 3-stage cp.async pipeline (R10 winner, unchanged)
// ---------------------------------------------------------------------------
#define SPADH  72
#define STG    3
#define TILE_H (128 * SPADH)
#define SMEM_GEMM (STG * 2 * TILE_H * 2)   // 110592 B

__device__ __forceinline__ void prefetch_chunk(const __half* __restrict__ A,
                                               const __half* __restrict__ B, int K,
                                               int mBase, int nBase, int kb,
                                               uint32_t sa, uint32_t sbm, int tid) {
#pragma unroll
    for (int i = 0; i < 4; i++) {
        int id = tid + i * 256;
        int row = id >> 3, c8 = id & 7;
        uint32_t so = (uint32_t)(row * SPADH + c8 * 8) * 2;
        CP_ASYNC16(sa  + so, A + (size_t)(mBase + row) * K + kb + c8 * 8);
        CP_ASYNC16(sbm + so, B + (size_t)(nBase + row) * K + kb + c8 * 8);
    }
}

__global__ void __launch_bounds__(256, 2)
gemm_f16(const __half* __restrict__ A, const __half* __restrict__ B,
         const float* __restrict__ bias, const float* __restrict__ res,
         float* __restrict__ Cf, __half* __restrict__ Ch,
         int N, int K, int doRelu)
{
    extern __shared__ __half smp[];
    const __half* sA[STG];
    const __half* sB[STG];
    uint32_t saA[STG], saB[STG];
#pragma unroll
    for (int s = 0; s < STG; s++) {
        sA[s] = smp + s * TILE_H;
        sB[s] = smp + (STG + s) * TILE_H;
        saA[s] = smem_u32(sA[s]);
        saB[s] = smem_u32(sB[s]);
    }

    int tid = threadIdx.x;
    int wid = tid >> 5, lane = tid & 31;
    int wm = wid & 1, wn = wid >> 1;
    int r = lane >> 2, kc = lane & 3;
    int mBase = blockIdx.y * 128, nBase = blockIdx.x * 128;

    float acc[4][4][4];
#pragma unroll
    for (int mt = 0; mt < 4; mt++)
#pragma unroll
        for (int nt = 0; nt < 4; nt++)
#pragma unroll
            for (int j = 0; j < 4; j++) acc[mt][nt][j] = 0.f;

    int NC = K >> 6;
    prefetch_chunk(A, B, K, mBase, nBase, 0,  saA[0], saB[0], tid);
    CP_COMMIT();
    prefetch_chunk(A, B, K, mBase, nBase, 64, saA[1], saB[1], tid);
    CP_COMMIT();

    for (int c = 0; c < NC; c++) {
        CP_WAIT(1);
        __syncthreads();

        if (c + 2 < NC)
            prefetch_chunk(A, B, K, mBase, nBase, (c + 2) * 64,
                           saA[(c + 2) % STG], saB[(c + 2) % STG], tid);
        CP_COMMIT();

        const __half* cA = sA[c % STG];
        const __half* cB = sB[c % STG];
#pragma unroll
        for (int ks = 0; ks < 4; ks++) {
            int k0 = ks * 16;
            uint32_t afr[4][4];
#pragma unroll
            for (int mt = 0; mt < 4; mt++) {
                int base = (wm * 64 + mt * 16 + r) * SPADH + k0 + 2 * kc;
                afr[mt][0] = *reinterpret_cast<const uint32_t*>(cA + base);
                afr[mt][1] = *reinterpret_cast<const uint32_t*>(cA + base + 8 * SPADH);
                afr[mt][2] = *reinterpret_cast<const uint32_t*>(cA + base + 8);
                afr[mt][3] = *reinterpret_cast<const uint32_t*>(cA + base + 8 * SPADH + 8);
            }
            uint32_t bfr[4][2];
#pragma unroll
            for (int nt = 0; nt < 4; nt++) {
                int base = (wn * 32 + nt * 8 + r) * SPADH + k0 + 2 * kc;
                bfr[nt][0] = *reinterpret_cast<const uint32_t*>(cB + base);
                bfr[nt][1] = *reinterpret_cast<const uint32_t*>(cB + base + 8);
            }
#pragma unroll
            for (int mt = 0; mt < 4; mt++)
#pragma unroll
                for (int nt = 0; nt < 4; nt++)
                    mma_f16(acc[mt][nt], afr[mt], bfr[nt]);
        }
    }

#pragma unroll
    for (int nt = 0; nt < 4; nt++) {
        int gc = nBase + wn * 32 + nt * 8 + kc * 2;
        float b0 = bias ? bias[gc]     : 0.f;
        float b1 = bias ? bias[gc + 1] : 0.f;
#pragma unroll
        for (int mt = 0; mt < 4; mt++) {
            int gr = mBase + wm * 64 + mt * 16 + r;
#pragma unroll
            for (int half = 0; half < 2; half++) {
                int row = gr + half * 8;
                float v0 = acc[mt][nt][half * 2 + 0] + b0;
                float v1 = acc[mt][nt][half * 2 + 1] + b1;
                if (doRelu) { v0 = fmaxf(v0, 0.f); v1 = fmaxf(v1, 0.f); }
                if (res) {
                    float2 rr = *reinterpret_cast<const float2*>(res + (size_t)row * N + gc);
                    v0 += rr.x; v1 += rr.y;
                }
                if (Cf) {
                    float2 o = { v0, v1 };
                    *reinterpret_cast<float2*>(Cf + (size_t)row * N + gc) = o;
                }
                if (Ch) {
                    __half2 o = { __float2half_rn(v0), __float2half_rn(v1) };
                    *reinterpret_cast<__half2*>(Ch + (size_t)row * N + gc) = o;
                }
            }
        }
    }
}

// ---------------------------------------------------------------------------
// Causal attention: block per (b,h), 320 threads = 1 query row each.
// f32x2-packed dot + PV accumulate; rescale only when running max changes.
// ---------------------------------------------------------------------------
__global__ void __launch_bounds__(TLEN, 1)
attn_kernel(const float* __restrict__ qkv, __half* __restrict__ outH) {
    extern __shared__ float sm[];
    float* Ks = sm;                  // [320][64]
    float* Vs = sm + TLEN * HSZ;

    int b = blockIdx.x / NH;
    int h = blockIdx.x % NH;
    size_t rowB = (size_t)b * TLEN;
    int hc = h * HSZ;

    int tid = threadIdx.x;
    for (int idx = tid; idx < TLEN * HSZ; idx += TLEN) {
        int rr = idx >> 6, d = idx & 63;
        size_t g = (rowB + rr) * NQKV + hc + d;
        Ks[idx] = qkv[g + 1024];
        Vs[idx] = qkv[g + 2048];
    }
    __syncthreads();

    int t = tid;
    uint64_t q2[32];
    {
        const float* qp = qkv + (rowB + t) * NQKV + hc;
#pragma unroll
        for (int i = 0; i < 32; i++) {
            float2 v = *reinterpret_cast<const float2*>(qp + 2 * i);
            PACK2XY(q2[i], v.x, v.y);
        }
    }

    float m = -1e30f, l = 0.f;
    uint64_t acc2[32];
#pragma unroll
    for (int i = 0; i < 32; i++) acc2[i] = 0ull;   // {0.f, 0.f}

    const float scale = 0.03125f;  // E^-0.5 (reference scales by full E)
    for (int s = 0; s <= t; s++) {
        const ulonglong2* kr = reinterpret_cast<const ulonglong2*>(Ks + s * HSZ);
        uint64_t dacc[4] = {0ull, 0ull, 0ull, 0ull};
#pragma unroll
        for (int j = 0; j < 16; j++) {
            ulonglong2 kk = kr[j];                 // LDS.128 -> 2 packed f32x2
            FMA2(dacc[(2 * j) & 3],     q2[2 * j],     kk.x);
            FMA2(dacc[(2 * j + 1) & 3], q2[2 * j + 1], kk.y);
        }
        float dot = 0.f;
#pragma unroll
        for (int j = 0; j < 4; j++) {
            float lo, hi; UNPACK2(lo, hi, dacc[j]);
            dot += lo + hi;
        }
        float sc = dot * scale;
        if (sc > m) {                // max changed: rescale (rare after warmup)
            float corr = __expf(m - sc);
            uint64_t c2; PACK2(c2, corr);
            l *= corr;
#pragma unroll
            for (int i = 0; i < 32; i++) MUL2(acc2[i], c2);
            m = sc;
        }
        float p = __expf(sc - m);
        l += p;
        uint64_t p2; PACK2(p2, p);
        const ulonglong2* vr = reinterpret_cast<const ulonglong2*>(Vs + s * HSZ);
#pragma unroll
        for (int j = 0; j < 16; j++) {
            ulonglong2 vv = vr[j];
            FMA2(acc2[2 * j],     p2, vv.x);
            FMA2(acc2[2 * j + 1], p2, vv.y);
        }
    }

    float invl = 1.f / l;
    size_t ob = (rowB + t) * EDIM + hc;
#pragma unroll
    for (int i = 0; i < 32; i++) {
        float lo, hi; UNPACK2(lo, hi, acc2[i]);
        __half2 o = { __float2half_rn(lo * invl), __float2half_rn(hi * invl) };
        *reinterpret_cast<__half2*>(outH + ob + 2 * i) = o;
    }
}

// ---------------------------------------------------------------------------
// Launch
// ---------------------------------------------------------------------------
extern "C" void kernel_launch(void* const* d_in, const int* in_sizes, int n_in,
                              void* d_out, int out_size) {
    const float* x    = (const float*)d_in[0];
    const float* Wq   = (const float*)d_in[1];
    const float* Wk   = (const float*)d_in[2];
    const float* Wv   = (const float*)d_in[3];
    const float* Wo   = (const float*)d_in[4];
    const float* bo   = (const float*)d_in[5];
    const float* W1   = (const float*)d_in[6];
    const float* b1   = (const float*)d_in[7];
    const float* W2   = (const float*)d_in[8];
    const float* b2   = (const float*)d_in[9];
    const float* ln1w = (const float*)d_in[10];
    const float* ln1b = (const float*)d_in[11];
    const float* ln2w = (const float*)d_in[12];
    const float* ln2b = (const float*)d_in[13];
    float* out = (float*)d_out;

    void* p;
#define SYMF(var, sym) cudaGetSymbolAddress(&p, sym); float* var = (float*)p;
#define SYMH(var, sym) cudaGetSymbolAddress(&p, sym); __half* var = (__half*)p;
    SYMH(h,    g_h)
    SYMF(qkv,  g_qkv)
    SYMH(at,   g_at)
    SYMF(x1,   g_x1)
    SYMH(u,    g_u)
    SYMH(Wqkv, g_Wqkv)
    SYMH(WoT,  g_Wo)
    SYMH(W1T,  g_W1)
    SYMH(W2T,  g_W2)
#undef SYMF
#undef SYMH

    const int smemAttn = 2 * TLEN * HSZ * (int)sizeof(float);  // 160 KB
    cudaFuncSetAttribute(attn_kernel, cudaFuncAttributeMaxDynamicSharedMemorySize, smemAttn);
    cudaFuncSetAttribute(gemm_f16, cudaFuncAttributeMaxDynamicSharedMemorySize, SMEM_GEMM);

    // Weight prep (fp16, [N,K] layout), tiled transposes
    qkv_transpose_tiled<<<dim3(EDIM / 32, 96), 256>>>(Wq, Wk, Wv, Wqkv);
    transpose_tiled<<<dim3(EDIM / 32, EDIM / 32), 256>>>(Wo, WoT, EDIM, EDIM);
    transpose_tiled<<<dim3(EDIM / 32, FF / 32),   256>>>(W1, W1T, EDIM, FF);
    transpose_tiled<<<dim3(FF / 32,   EDIM / 32), 256>>>(W2, W2T, FF, EDIM);

    dim3 blk(256);
    // 1) LN1 -> h (fp16)
    ln_kernel<<<MTOK, 256>>>(x, ln1w, ln1b, h);
    // 2) fused QKV: [M,1024] x [3072,1024]^T -> qkv fp32
    gemm_f16<<<dim3(NQKV / 128, MTOK / 128), blk, SMEM_GEMM>>>(
        h, Wqkv, nullptr, nullptr, qkv, nullptr, NQKV, EDIM, 0);
    // 3) attention -> at (fp16)
    attn_kernel<<<64 * NH, TLEN, smemAttn>>>(qkv, at);
    // 4) O-proj + bo + residual(x) -> x1 fp32
    gemm_f16<<<dim3(EDIM / 128, MTOK / 128), blk, SMEM_GEMM>>>(
        at, WoT, bo, x, x1, nullptr, EDIM, EDIM, 0);
    // 5) LN2 -> h (fp16)
    ln_kernel<<<MTOK, 256>>>(x1, ln2w, ln2b, h);
    // 6) FFN up + b1 + ReLU -> u (fp16)
    gemm_f16<<<dim3(FF / 128, MTOK / 128), blk, SMEM_GEMM>>>(
        h, W1T, b1, nullptr, nullptr, u, FF, EDIM, 1);
    // 7) FFN down + b2 + residual(x1) -> out fp32
    gemm_f16<<<dim3(EDIM / 128, MTOK / 128), blk, SMEM_GEMM>>>(
        u, W2T, b2, x1, out, nullptr, EDIM, FF, 0);
}